// round 5
// baseline (speedup 1.0000x reference)
#include <cuda_runtime.h>
#include <cuda_bf16.h>
#include <cstdint>

// AttentionLayer_50989851738889
//
// Mathematical reduction (verified bit-exact, rel_err = 0.0 in R1/R2):
//   a = e / sum(e, axis=-1, keepdims=True) over a SIZE-1 axis -> a = e/e = 1.0
//   exactly (g = sum_u tanh(.)*Wa[u] is bounded, so e = exp(max g) is finite
//   and nonzero; IEEE x/x == 1.0). v = a * inputs == inputs bit-for-bit.
//   Output is a pure copy of d_in[0] (B*L*D = 2097152 fp32 = 8 MB).
//
// R1/R2 post-mortem: SM copy kernels are launch/ramp dominated (issue 4.6%,
// DRAM 18% — nowhere near the BW roofline). Mechanism under test (R3/R4,
// unmeasured due to infra timeouts): bypass the SM path with an async D2D
// memcpy, which graph-captures as a memcpy node (copy-engine or
// driver-optimized path). Explicitly allowed by the harness rules
// ("cudaMemcpyAsync device-to-device ... are fine").

extern "C" void kernel_launch(void* const* d_in, const int* in_sizes, int n_in,
                              void* d_out, int out_size) {
    const void* src = d_in[0];
    size_t bytes = (size_t)out_size * sizeof(float);  // 8 MB
    cudaMemcpyAsync(d_out, src, bytes, cudaMemcpyDeviceToDevice, 0);
}

// round 8
// speedup vs baseline: 1.1490x; 1.1490x over previous
#include <cuda_runtime.h>
#include <cuda_bf16.h>
#include <cstdint>

// AttentionLayer_50989851738889
//
// Mathematical reduction (verified bit-exact, rel_err = 0.0 across rounds):
//   a = e / sum(e, axis=-1, keepdims=True) over a SIZE-1 axis -> a = e/e = 1.0
//   exactly (g = sum_u tanh(.)*Wa[u] is bounded, so e = exp(max g) is finite
//   nonzero; IEEE x/x == 1.0). v = a * inputs == inputs bit-for-bit.
//   Output is a pure copy of d_in[0] (B*L*D = 2097152 fp32 = 8 MB).
//
// Measured: SM copy MLP=1 -> 6.21us kernel; MLP=4 -> 5.89us; graph memcpy
// node -> 7.65us total (dead end, reverted). Under test (4th submission;
// prior three lost to broker timeouts): MLP=8 point. 256 CTAs x 256 thr x 8
// front-batched LDG.128 = 524288 float4 exact, single wave.

__global__ void __launch_bounds__(256) copy_kernel_v4x8(
    const float4* __restrict__ src, float4* __restrict__ dst, int n4) {
    const int t = blockIdx.x * blockDim.x + threadIdx.x;
    const int s = gridDim.x * blockDim.x;  // 65536

    if (8 * s == n4) {
        // 8 independent loads batched up front -> 8 outstanding LDG.128/thread
        float4 r0 = src[t];
        float4 r1 = src[t + s];
        float4 r2 = src[t + 2 * s];
        float4 r3 = src[t + 3 * s];
        float4 r4 = src[t + 4 * s];
        float4 r5 = src[t + 5 * s];
        float4 r6 = src[t + 6 * s];
        float4 r7 = src[t + 7 * s];
        dst[t]         = r0;
        dst[t + s]     = r1;
        dst[t + 2 * s] = r2;
        dst[t + 3 * s] = r3;
        dst[t + 4 * s] = r4;
        dst[t + 5 * s] = r5;
        dst[t + 6 * s] = r6;
        dst[t + 7 * s] = r7;
    } else {
        // Generic fallback (never taken for the fixed shape)
        for (int i = t; i < n4; i += s) dst[i] = src[i];
    }
}

extern "C" void kernel_launch(void* const* d_in, const int* in_sizes, int n_in,
                              void* d_out, int out_size) {
    const float4* src = (const float4*)d_in[0];
    float4* dst = (float4*)d_out;

    int n4 = out_size >> 2;  // 524288 float4

    const int threads = 256;
    const int blocks = 256;  // 256*256*8 == 524288 exactly; single wave
    copy_kernel_v4x8<<<blocks, threads>>>(src, dst, n4);
}